// round 12
// baseline (speedup 1.0000x reference)
#include <cuda_runtime.h>
#include <math.h>

#define NN 50000
#define EE 400000
#define TT 4
#define F0 128
#define F2 64

// ---------------- device scratch (no allocs allowed) ----------------
__device__ float g_scores0[TT * NN];
__device__ float g_scores1[TT * NN];
__device__ int   g_idx0[128];
__device__ float g_tv0[128];
__device__ int   g_idx1[128];
__device__ float g_tv1[128];
__device__ float g_inv[2];
__device__ float g_Q0s[TT][128 * 128];
__device__ float g_Q1s[TT][128 * 64];
__device__ float g_XW0[2][(size_t)NN * 128];   // double-buffered layer-0 XW
__device__ float g_XW1[2][(size_t)NN * 64];    // double-buffered layer-1 XW
__device__ float g_h1[TT][NN * 128];
__device__ int   g_rowptr[TT][NN + 1];
__device__ int   g_cursor[TT][NN];
__device__ int   g_eid[TT][EE];

// ---------------- helpers ----------------
__device__ __forceinline__ unsigned sortable_u32(float f) {
    unsigned u = __float_as_uint(f);
    return (u & 0x80000000u) ? ~u : (u | 0x80000000u);
}

// ---------------- scorer norms ----------------
__global__ void norm_kernel(const float* __restrict__ s0, const float* __restrict__ s1,
                            float* __restrict__ inv) {
    const float* s = blockIdx.x ? s1 : s0;
    int t = threadIdx.x;           // 128 threads
    float v = s[t]; v *= v;
    __shared__ float red[4];
    for (int o = 16; o; o >>= 1) v += __shfl_xor_sync(0xFFFFFFFFu, v, o);
    if ((t & 31) == 0) red[t >> 5] = v;
    __syncthreads();
    if (t == 0) inv[blockIdx.x] = rsqrtf(red[0] + red[1] + red[2] + red[3]);
}

// ---------------- scores (generic): one warp per node ----------------
__global__ __launch_bounds__(256) void scores_kernel(
    const float* __restrict__ X, const float* __restrict__ scorer,
    const float* __restrict__ mask_t, const float* __restrict__ invp,
    float* __restrict__ out) {
    int warp = (blockIdx.x * blockDim.x + threadIdx.x) >> 5;
    int lane = threadIdx.x & 31;
    if (warp >= NN) return;
    float4 x = reinterpret_cast<const float4*>(X)[(size_t)warp * 32 + lane];
    float4 s = reinterpret_cast<const float4*>(scorer)[lane];
    float d = x.x * s.x + x.y * s.y + x.z * s.z + x.w * s.w;
    for (int o = 16; o; o >>= 1) d += __shfl_xor_sync(0xFFFFFFFFu, d, o);
    if (lane == 0) out[warp] = d * (*invp) + mask_t[warp];
}

// ---------------- scores for ALL layer-0 timesteps in one launch ----------------
__global__ __launch_bounds__(256) void scores0_all_kernel(
    const float* __restrict__ X, const float* __restrict__ scorer,
    const float* __restrict__ mask, const float* __restrict__ invp,
    float* __restrict__ out) {
    int warp = (blockIdx.x * blockDim.x + threadIdx.x) >> 5;  // flat (t,node)
    int lane = threadIdx.x & 31;
    if (warp >= TT * NN) return;
    float4 x = reinterpret_cast<const float4*>(X)[(size_t)warp * 32 + lane];
    float4 s = reinterpret_cast<const float4*>(scorer)[lane];
    float d = x.x * s.x + x.y * s.y + x.z * s.z + x.w * s.w;
    for (int o = 16; o; o >>= 1) d += __shfl_xor_sync(0xFFFFFFFFu, d, o);
    if (lane == 0) out[warp] = d * invp[0] + mask[warp];
}

// ---------------- fused single-block topk ----------------
__global__ __launch_bounds__(1024) void topk_kernel(
    const float* __restrict__ scores, int k,
    int* __restrict__ idx_out, float* __restrict__ tv_out) {
    __shared__ unsigned h1[1024];
    __shared__ unsigned csum[1024];
    __shared__ unsigned h2[64];
    __shared__ unsigned long long sk[4096];
    __shared__ int s_cb, s_kAbove, s_T16, s_cnt;
    int tid = threadIdx.x;
    h1[tid] = 0;
    if (tid < 64) h2[tid] = 0;
    if (tid == 0) s_cnt = 0;
    __syncthreads();

    const float4* s4 = reinterpret_cast<const float4*>(scores);
    for (int i = tid; i < NN / 4; i += 1024) {
        float4 v = s4[i];
        atomicAdd(&h1[sortable_u32(v.x) >> 22], 1u);
        atomicAdd(&h1[sortable_u32(v.y) >> 22], 1u);
        atomicAdd(&h1[sortable_u32(v.z) >> 22], 1u);
        atomicAdd(&h1[sortable_u32(v.w) >> 22], 1u);
    }
    __syncthreads();
    csum[tid] = h1[tid];
    __syncthreads();
    for (int off = 1; off < 1024; off <<= 1) {
        unsigned v = (tid + off < 1024) ? csum[tid + off] : 0u;
        __syncthreads();
        csum[tid] += v;
        __syncthreads();
    }
    unsigned above = (tid < 1023) ? csum[tid + 1] : 0u;
    if (csum[tid] >= (unsigned)k && above < (unsigned)k) { s_cb = tid; s_kAbove = (int)above; }
    __syncthreads();
    int cb = s_cb;
    unsigned kAbove = (unsigned)s_kAbove;

    for (int i = tid; i < NN / 4; i += 1024) {
        float4 v = s4[i];
        unsigned u;
        u = sortable_u32(v.x); if ((int)(u >> 22) == cb) atomicAdd(&h2[(u >> 16) & 63], 1u);
        u = sortable_u32(v.y); if ((int)(u >> 22) == cb) atomicAdd(&h2[(u >> 16) & 63], 1u);
        u = sortable_u32(v.z); if ((int)(u >> 22) == cb) atomicAdd(&h2[(u >> 16) & 63], 1u);
        u = sortable_u32(v.w); if ((int)(u >> 22) == cb) atomicAdd(&h2[(u >> 16) & 63], 1u);
    }
    __syncthreads();
    if (tid == 0) {
        unsigned run = kAbove;
        int f = 0;
        for (int b = 63; b >= 0; b--) {
            run += h2[b];
            if (run >= (unsigned)k) { f = b; break; }
        }
        s_T16 = (cb << 6) | f;
    }
    __syncthreads();
    int T16 = s_T16;

    for (int i = tid; i < NN / 4; i += 1024) {
        float4 v = s4[i];
        float vs[4] = {v.x, v.y, v.z, v.w};
#pragma unroll
        for (int c = 0; c < 4; c++) {
            unsigned u = sortable_u32(vs[c]);
            if ((int)(u >> 16) >= T16) {
                int p = atomicAdd(&s_cnt, 1);
                if (p < 4096) {
                    unsigned idx = (unsigned)(i * 4 + c);
                    sk[p] = ((unsigned long long)u << 32) |
                            (unsigned long long)(0xFFFFFFFFu - idx);
                }
            }
        }
    }
    __syncthreads();
    int cnt = s_cnt; if (cnt > 4096) cnt = 4096;
    int n = k; while (n < cnt) n <<= 1;
    for (int i = tid; i < n; i += 1024) if (i >= cnt) sk[i] = 0ULL;
    __syncthreads();
    for (int size = 2; size <= n; size <<= 1) {
        for (int stride = size >> 1; stride; stride >>= 1) {
            for (int i = tid; i < n; i += 1024) {
                int j = i ^ stride;
                if (j > i) {
                    bool asc = (i & size) != 0;
                    unsigned long long a = sk[i], b = sk[j];
                    if ((a > b) == asc) { sk[i] = b; sk[j] = a; }
                }
            }
            __syncthreads();
        }
    }
    if (tid < k) {
        unsigned long long key = sk[tid];
        int idx = (int)(0xFFFFFFFFu - (unsigned)(key & 0xFFFFFFFFu));
        if (idx < 0) idx = 0; if (idx >= NN) idx = NN - 1;   // safety
        idx_out[tid] = idx;
        tv_out[tid] = tanhf(scores[idx]);
    }
}

// ---------------- matrix GRU: one block per output column ----------------
template <int COLS>
__global__ __launch_bounds__(128) void gru_kernel(
    const float* __restrict__ X,
    const int* __restrict__ idx, const float* __restrict__ tv,
    const float* __restrict__ Wu, const float* __restrict__ Uu, const float* __restrict__ Bu,
    const float* __restrict__ Wr, const float* __restrict__ Ur, const float* __restrict__ Br,
    const float* __restrict__ Wh, const float* __restrict__ Uh, const float* __restrict__ Bh,
    const float* __restrict__ Qin, float* __restrict__ Qout) {
    __shared__ __align__(16) float zs[128];
    __shared__ __align__(16) float qs[128];
    __shared__ __align__(16) float rq[128];
    int c = blockIdx.x, r = threadIdx.x;
    zs[r] = X[(size_t)idx[c] * 128 + r] * tv[c];
    float q = Qin[r * COLS + c];
    qs[r] = q;
    __syncthreads();

    const float4* zr  = reinterpret_cast<const float4*>(zs);
    const float4* qr  = reinterpret_cast<const float4*>(qs);
    const float4* pwu = reinterpret_cast<const float4*>(Wu + r * 128);
    const float4* puu = reinterpret_cast<const float4*>(Uu + r * 128);
    const float4* pwr = reinterpret_cast<const float4*>(Wr + r * 128);
    const float4* pur = reinterpret_cast<const float4*>(Ur + r * 128);
    const float4* pwh = reinterpret_cast<const float4*>(Wh + r * 128);
    float au = 0.f, ar = 0.f, hw = 0.f;
#pragma unroll 8
    for (int i = 0; i < 32; i++) {
        float4 z4 = zr[i], q4 = qr[i];
        float4 a = pwu[i]; au += a.x * z4.x + a.y * z4.y + a.z * z4.z + a.w * z4.w;
        float4 b = puu[i]; au += b.x * q4.x + b.y * q4.y + b.z * q4.z + b.w * q4.w;
        float4 cc = pwr[i]; ar += cc.x * z4.x + cc.y * z4.y + cc.z * z4.z + cc.w * z4.w;
        float4 d = pur[i]; ar += d.x * q4.x + d.y * q4.y + d.z * q4.z + d.w * q4.w;
        float4 e = pwh[i]; hw += e.x * z4.x + e.y * z4.y + e.z * z4.z + e.w * z4.w;
    }
    float upd = 1.f / (1.f + expf(-(au + Bu[r * COLS + c])));
    float rst = 1.f / (1.f + expf(-(ar + Br[r * COLS + c])));
    rq[r] = rst * q;
    __syncthreads();
    const float4* puh = reinterpret_cast<const float4*>(Uh + r * 128);
    const float4* rq4 = reinterpret_cast<const float4*>(rq);
    float hu = 0.f;
#pragma unroll 8
    for (int i = 0; i < 32; i++) {
        float4 a = puh[i]; float4 v = rq4[i];
        hu += a.x * v.x + a.y * v.y + a.z * v.z + a.w * v.w;
    }
    float hcap = tanhf(hw + hu + Bh[r * COLS + c]);
    Qout[r * COLS + c] = (1.f - upd) * q + upd * hcap;
}

// ---------------- GEMM: XW[N,BN] = X[N,128] @ Q[128,BN], K chunked 2x64 ----------------
template <int BN, int TN>
__global__ __launch_bounds__(256) void gemm_kernel(
    const float* __restrict__ X, const float* __restrict__ Q,
    float* __restrict__ XW, int n) {
    constexpr int PITCH = 132;
    extern __shared__ float smem[];
    float* Xs = smem;                     // [64][PITCH] transposed: Xs[k][m]
    float* Qs = smem + 64 * PITCH;        // [128][BN]
    const int tid = threadIdx.x;
    const int tx = tid & 15, ty = tid >> 4;
    const int m0 = blockIdx.x * 128;

    constexpr int QF4 = 128 * BN / 4;
    for (int f = tid; f < QF4; f += 256)
        reinterpret_cast<float4*>(Qs)[f] = reinterpret_cast<const float4*>(Q)[f];

    float acc[8][TN];
#pragma unroll
    for (int i = 0; i < 8; i++)
#pragma unroll
        for (int j = 0; j < TN; j++) acc[i][j] = 0.f;

    const int mb = ty * 8, nb = tx * TN;

#pragma unroll
    for (int kc = 0; kc < 2; kc++) {
        if (kc) __syncthreads();          // WAR: prev chunk's reads done
#pragma unroll
        for (int it = 0; it < 8; ++it) {
            int f = it * 256 + tid;
            int m = f >> 4, k4 = f & 15;
            float4 v = make_float4(0.f, 0.f, 0.f, 0.f);
            int gm = m0 + m;
            if (gm < n) v = reinterpret_cast<const float4*>(X)[(size_t)gm * 32 + kc * 16 + k4];
            int k = k4 * 4;
            Xs[(k + 0) * PITCH + m] = v.x;
            Xs[(k + 1) * PITCH + m] = v.y;
            Xs[(k + 2) * PITCH + m] = v.z;
            Xs[(k + 3) * PITCH + m] = v.w;
        }
        __syncthreads();
#pragma unroll 4
        for (int k = 0; k < 64; k++) {
            float a[8], b[TN];
            float4 a0 = *reinterpret_cast<const float4*>(&Xs[k * PITCH + mb]);
            float4 a1 = *reinterpret_cast<const float4*>(&Xs[k * PITCH + mb + 4]);
            a[0] = a0.x; a[1] = a0.y; a[2] = a0.z; a[3] = a0.w;
            a[4] = a1.x; a[5] = a1.y; a[6] = a1.z; a[7] = a1.w;
#pragma unroll
            for (int j4 = 0; j4 < TN / 4; j4++) {
                float4 bq = *reinterpret_cast<const float4*>(&Qs[(kc * 64 + k) * BN + nb + j4 * 4]);
                b[j4 * 4 + 0] = bq.x; b[j4 * 4 + 1] = bq.y;
                b[j4 * 4 + 2] = bq.z; b[j4 * 4 + 3] = bq.w;
            }
#pragma unroll
            for (int i = 0; i < 8; i++)
#pragma unroll
                for (int j = 0; j < TN; j++)
                    acc[i][j] = fmaf(a[i], b[j], acc[i][j]);
        }
    }

#pragma unroll
    for (int i = 0; i < 8; i++) {
        int gm = m0 + mb + i;
        if (gm < n) {
#pragma unroll
            for (int j4 = 0; j4 < TN / 4; j4++) {
                float4 o;
                o.x = acc[i][j4 * 4 + 0]; o.y = acc[i][j4 * 4 + 1];
                o.z = acc[i][j4 * 4 + 2]; o.w = acc[i][j4 * 4 + 3];
                reinterpret_cast<float4*>(XW + (size_t)gm * BN + nb)[j4] = o;
            }
        }
    }
}

// ---------------- batched CSR build (all timesteps) ----------------
__global__ void deg_all_kernel(const int* __restrict__ dst, int* __restrict__ deg) {
    int i = blockIdx.x * blockDim.x + threadIdx.x;   // flat (t,e)
    if (i < TT * EE) {
        int t = i / EE;
        atomicAdd(&deg[t * NN + dst[i]], 1);
    }
}

__global__ __launch_bounds__(1024) void scan_all_kernel(int* __restrict__ deg_all,
                                                        int* __restrict__ rowptr_all) {
    __shared__ int sums[1024];
    int* deg = deg_all + blockIdx.x * NN;
    int* rowptr = rowptr_all + blockIdx.x * (NN + 1);
    int tid = threadIdx.x;
    const int CH = (NN + 1023) / 1024;   // 49
    int s0 = tid * CH;
    int s = 0;
    for (int j = 0; j < CH; j++) {
        int i = s0 + j;
        if (i < NN) s += deg[i];
    }
    sums[tid] = s;
    __syncthreads();
    for (int off = 1; off < 1024; off <<= 1) {
        int v = (tid >= off) ? sums[tid - off] : 0;
        __syncthreads();
        sums[tid] += v;
        __syncthreads();
    }
    int run = (tid == 0) ? 0 : sums[tid - 1];
    for (int j = 0; j < CH; j++) {
        int i = s0 + j;
        if (i < NN) {
            int d = deg[i];
            rowptr[i] = run;
            deg[i] = run;    // cursor
            run += d;
        }
    }
    if (tid == 1023) rowptr[NN] = sums[1023];
}

__global__ void fill_all_kernel(const int* __restrict__ dst, int* __restrict__ cursor,
                                int* __restrict__ eid) {
    int i = blockIdx.x * blockDim.x + threadIdx.x;   // flat (t,e)
    if (i < TT * EE) {
        int t = i / EE, e = i - t * EE;
        int p = atomicAdd(&cursor[t * NN + dst[i]], 1);
        eid[t * EE + p] = e;
    }
}

// ---------------- gather: out[d] = relu(sum_{e: dst==d} w_e * XW[src_e]) ----------------
template <int COLS>
__global__ __launch_bounds__(256) void gather_kernel(
    const float* __restrict__ XW, const int* __restrict__ src,
    const float* __restrict__ ew, const int* __restrict__ rowptr,
    const int* __restrict__ eid, float* __restrict__ out) {
    constexpr int L = COLS / 4;          // lanes per node
    constexpr int NPW = 32 / L;          // nodes per warp
    int warp = (blockIdx.x * blockDim.x + threadIdx.x) >> 5;
    int lane = threadIdx.x & 31;
    int node = warp * NPW + lane / L;
    int cl = lane % L;
    if (node >= NN) return;
    int b = rowptr[node], e2 = rowptr[node + 1];
    float4 acc = make_float4(0.f, 0.f, 0.f, 0.f);
    const float4* XW4 = reinterpret_cast<const float4*>(XW);
    for (int j = b; j < e2; j++) {
        int e = eid[j];
        int s = src[e];
        float w = ew[e];
        float4 v = XW4[(size_t)s * L + cl];
        acc.x = fmaf(w, v.x, acc.x);
        acc.y = fmaf(w, v.y, acc.y);
        acc.z = fmaf(w, v.z, acc.z);
        acc.w = fmaf(w, v.w, acc.w);
    }
    acc.x = fmaxf(acc.x, 0.f); acc.y = fmaxf(acc.y, 0.f);
    acc.z = fmaxf(acc.z, 0.f); acc.w = fmaxf(acc.w, 0.f);
    reinterpret_cast<float4*>(out)[(size_t)node * L + cl] = acc;
}

// ---------------- host orchestration ----------------
extern "C" void kernel_launch(void* const* d_in, const int* in_sizes, int n_in,
                              void* d_out, int out_size) {
    const float* node_embs = (const float*)d_in[0];
    const float* mask      = (const float*)d_in[1];
    const int*   esrc      = (const int*)d_in[2];
    const int*   edst      = (const int*)d_in[3];
    const float* ew        = (const float*)d_in[4];
    const float* gcn_w0    = (const float*)d_in[5];
    const float* gcn_w1    = (const float*)d_in[6];
    const float* L0[10]; for (int i = 0; i < 10; i++) L0[i] = (const float*)d_in[7 + i];
    const float* L1[10]; for (int i = 0; i < 10; i++) L1[i] = (const float*)d_in[17 + i];
    float* out = (float*)d_out;

    float *scores0, *scores1, *tv0, *tv1, *inv, *q0s, *q1s, *xw0, *xw1, *h1;
    int *idx0, *idx1, *rowptr, *cursor, *eid;
    cudaGetSymbolAddress((void**)&scores0, g_scores0);
    cudaGetSymbolAddress((void**)&scores1, g_scores1);
    cudaGetSymbolAddress((void**)&idx0,    g_idx0);
    cudaGetSymbolAddress((void**)&tv0,     g_tv0);
    cudaGetSymbolAddress((void**)&idx1,    g_idx1);
    cudaGetSymbolAddress((void**)&tv1,     g_tv1);
    cudaGetSymbolAddress((void**)&inv,     g_inv);
    cudaGetSymbolAddress((void**)&q0s,     g_Q0s);
    cudaGetSymbolAddress((void**)&q1s,     g_Q1s);
    cudaGetSymbolAddress((void**)&xw0,     g_XW0);
    cudaGetSymbolAddress((void**)&xw1,     g_XW1);
    cudaGetSymbolAddress((void**)&h1,      g_h1);
    cudaGetSymbolAddress((void**)&rowptr,  g_rowptr);
    cudaGetSymbolAddress((void**)&cursor,  g_cursor);
    cudaGetSymbolAddress((void**)&eid,     g_eid);

    // one-time host objects — SAME footprint class as the passing R9 config:
    // exactly ONE extra stream, 18 events. (5 streams tripped the harness's
    // device-memory guard by ~2 MiB; stream creation is the dominant cost.)
    static cudaStream_t sB = nullptr;
    static cudaEvent_t evStart, evEnd;
    static cudaEvent_t eGemm0[TT], eGemm1[TT], eGru1[TT], eGath1[TT];
    if (!sB) {
        cudaStreamCreateWithFlags(&sB, cudaStreamNonBlocking);
        cudaEventCreateWithFlags(&evStart, cudaEventDisableTiming);
        cudaEventCreateWithFlags(&evEnd,   cudaEventDisableTiming);
        for (int t = 0; t < TT; t++) {
            cudaEventCreateWithFlags(&eGemm0[t], cudaEventDisableTiming);
            cudaEventCreateWithFlags(&eGemm1[t], cudaEventDisableTiming);
            cudaEventCreateWithFlags(&eGru1[t],  cudaEventDisableTiming);
            cudaEventCreateWithFlags(&eGath1[t], cudaEventDisableTiming);
        }
    }

    size_t sm128 = (size_t)(64 * 132 + 128 * 128) * sizeof(float);  // 99328
    size_t sm64  = (size_t)(64 * 132 + 128 * 64)  * sizeof(float);  // 66560
    cudaFuncSetAttribute(gemm_kernel<128, 8>, cudaFuncAttributeMaxDynamicSharedMemorySize, (int)sm128);
    cudaFuncSetAttribute(gemm_kernel<64, 4>,  cudaFuncAttributeMaxDynamicSharedMemorySize, (int)sm64);

    const int gblocks = (NN + 127) / 128;
    const int gth128  = ((NN * 32 + 255) / 256);             // 1 node/warp
    const int gth64   = ((((NN + 1) / 2) * 32 + 255) / 256); // 2 nodes/warp

    // ---- fork sB from origin ----
    cudaEventRecord(evStart, 0);
    cudaStreamWaitEvent(sB, evStart, 0);

    // sB: batched CSR for all timesteps (its gathers follow in-order)
    cudaMemsetAsync(cursor, 0, (size_t)TT * NN * sizeof(int), sB);
    deg_all_kernel<<<(TT * EE + 255) / 256, 256, 0, sB>>>(edst, cursor);
    scan_all_kernel<<<TT, 1024, 0, sB>>>(cursor, rowptr);
    fill_all_kernel<<<(TT * EE + 255) / 256, 256, 0, sB>>>(edst, cursor, eid);

    // origin: norms + all layer-0 scores + layer-0 small chain (runs ahead)
    norm_kernel<<<2, 128>>>(L0[9], L1[9], inv);
    scores0_all_kernel<<<(TT * NN + 7) / 8, 256>>>(node_embs, L0[9], mask, inv, scores0);
    for (int t = 0; t < TT; t++) {
        const float* Xt   = node_embs + (size_t)t * NN * F0;
        const float* q0in = (t == 0) ? gcn_w0 : (q0s + (size_t)(t - 1) * 128 * 128);
        float*       q0out = q0s + (size_t)t * 128 * 128;
        topk_kernel<<<1, 1024>>>(scores0 + (size_t)t * NN, 128, idx0, tv0);
        gru_kernel<128><<<128, 128>>>(Xt, idx0, tv0, L0[0], L0[1], L0[2], L0[3], L0[4],
                                      L0[5], L0[6], L0[7], L0[8], q0in, q0out);
    }

    // ---- helpers to emit pipeline stages ----
    auto emitG0 = [&](int t) {   // origin: gemm128(t)
        const float* Xt = node_embs + (size_t)t * NN * F0;
        float* xw0t = xw0 + (size_t)(t & 1) * NN * 128;
        // XW0 reuse vs gather128(t-2): covered transitively — G1(t-2) was
        // issued earlier on origin and waited on eGru1[t-2] ⊇ gather128(t-2).
        gemm_kernel<128, 8><<<gblocks, 256, sm128, 0>>>(Xt, q0s + (size_t)t * 128 * 128, xw0t, NN);
        cudaEventRecord(eGemm0[t], 0);
    };
    auto emitG1 = [&](int t) {   // origin: gemm64(t)
        float* h1t = h1 + (size_t)t * NN * 128;
        float* xw1t = xw1 + (size_t)(t & 1) * NN * 64;
        cudaStreamWaitEvent(0, eGru1[t], 0);             // gru1(t) ⊇ gather128(t) ⊇ h1t ready
        if (t >= 2) cudaStreamWaitEvent(0, eGath1[t - 2], 0);  // XW1 buffer reuse
        gemm_kernel<64, 4><<<gblocks, 256, sm64, 0>>>(h1t, q1s + (size_t)t * 128 * 64, xw1t, NN);
        cudaEventRecord(eGemm1[t], 0);
    };
    auto emitA0chain = [&](int t) {  // sB: gather128 + scores1 + topk1 + gru1
        float* h1t = h1 + (size_t)t * NN * 128;
        float* xw0t = xw0 + (size_t)(t & 1) * NN * 128;
        const float* q1in = (t == 0) ? gcn_w1 : (q1s + (size_t)(t - 1) * 128 * 64);
        cudaStreamWaitEvent(sB, eGemm0[t], 0);
        gather_kernel<128><<<gth128, 256, 0, sB>>>(xw0t, esrc + (size_t)t * EE,
                                                   ew + (size_t)t * EE,
                                                   rowptr + (size_t)t * (NN + 1),
                                                   eid + (size_t)t * EE, h1t);
        scores_kernel<<<(NN + 7) / 8, 256, 0, sB>>>(h1t, L1[9], mask + (size_t)t * NN,
                                                    inv + 1, scores1 + (size_t)t * NN);
        topk_kernel<<<1, 1024, 0, sB>>>(scores1 + (size_t)t * NN, 64, idx1, tv1);
        gru_kernel<64><<<64, 128, 0, sB>>>(h1t, idx1, tv1, L1[0], L1[1], L1[2], L1[3], L1[4],
                                           L1[5], L1[6], L1[7], L1[8], q1in,
                                           q1s + (size_t)t * 128 * 64);
        cudaEventRecord(eGru1[t], sB);
    };
    auto emitA1 = [&](int t) {   // sB: gather64(t) -> out[t]
        float* xw1t = xw1 + (size_t)(t & 1) * NN * 64;
        cudaStreamWaitEvent(sB, eGemm1[t], 0);
        gather_kernel<64><<<gth64, 256, 0, sB>>>(xw1t, esrc + (size_t)t * EE,
                                                 ew + (size_t)t * EE,
                                                 rowptr + (size_t)t * (NN + 1),
                                                 eid + (size_t)t * EE,
                                                 out + (size_t)t * NN * F2);
        cudaEventRecord(eGath1[t], sB);
    };

    // ---- interleaved pipeline issue (cycle-free: every cross-stream wait
    //      points strictly backward in the partner stream's issue order) ----
    // origin: G0(0) G0(1) G1(0) G0(2) G1(1) G0(3) G1(2) G1(3)
    // sB:     A0(0) A0(1) A1(0) A0(2) A1(1) A0(3) A1(2) A1(3)   (A0 = gather+scores+topk+gru chain)
    emitG0(0);
    emitA0chain(0);
    emitG0(1);
    emitA0chain(1);
    emitG1(0);
    emitA1(0);
    emitG0(2);
    emitA0chain(2);
    emitG1(1);
    emitA1(1);
    emitG0(3);
    emitA0chain(3);
    emitG1(2);
    emitA1(2);
    emitG1(3);
    emitA1(3);

    // ---- join sB back into origin ----
    cudaEventRecord(evEnd, sB);
    cudaStreamWaitEvent(0, evEnd, 0);
}

// round 15
// speedup vs baseline: 1.1777x; 1.1777x over previous
#include <cuda_runtime.h>
#include <math.h>

#define NN 50000
#define EE 400000
#define TT 4
#define F0 128
#define F2 64

// ---------------- device scratch (no allocs allowed) ----------------
__device__ float g_scores0[TT * NN];
__device__ float g_scores1[TT * NN];
__device__ int   g_idx0[TT * 128];
__device__ float g_tv0[TT * 128];
__device__ int   g_idx1[TT * 64];
__device__ float g_tv1[TT * 64];
__device__ float g_inv[2];
__device__ float g_Q0s[TT][128 * 128];
__device__ float g_Q1s[TT][128 * 64];
__device__ float g_AX[TT][(size_t)NN * 128];   // A(t) @ X(t)   (pre-aggregated input)
__device__ float g_h1[TT][(size_t)NN * 128];   // relu(AX @ Q0)
__device__ float g_XW1[TT][(size_t)NN * 64];   // h1 @ Q1
__device__ int   g_rowptr[TT][NN + 1];
__device__ int   g_cursor[TT][NN];
__device__ int   g_csrc[TT][EE];               // CSR-ordered src (no eid indirection)
__device__ float g_csrw[TT][EE];               // CSR-ordered weight

// ---------------- helpers ----------------
__device__ __forceinline__ unsigned sortable_u32(float f) {
    unsigned u = __float_as_uint(f);
    return (u & 0x80000000u) ? ~u : (u | 0x80000000u);
}

// ---------------- scorer norms ----------------
__global__ void norm_kernel(const float* __restrict__ s0, const float* __restrict__ s1,
                            float* __restrict__ inv) {
    const float* s = blockIdx.x ? s1 : s0;
    int t = threadIdx.x;           // 128 threads
    float v = s[t]; v *= v;
    __shared__ float red[4];
    for (int o = 16; o; o >>= 1) v += __shfl_xor_sync(0xFFFFFFFFu, v, o);
    if ((t & 31) == 0) red[t >> 5] = v;
    __syncthreads();
    if (t == 0) inv[blockIdx.x] = rsqrtf(red[0] + red[1] + red[2] + red[3]);
}

// ---------------- scores for ALL layer-0 timesteps ----------------
__global__ __launch_bounds__(256) void scores0_all_kernel(
    const float* __restrict__ X, const float* __restrict__ scorer,
    const float* __restrict__ mask, const float* __restrict__ invp,
    float* __restrict__ out) {
    int warp = (blockIdx.x * blockDim.x + threadIdx.x) >> 5;  // flat (t,node)
    int lane = threadIdx.x & 31;
    if (warp >= TT * NN) return;
    float4 x = reinterpret_cast<const float4*>(X)[(size_t)warp * 32 + lane];
    float4 s = reinterpret_cast<const float4*>(scorer)[lane];
    float d = x.x * s.x + x.y * s.y + x.z * s.z + x.w * s.w;
    for (int o = 16; o; o >>= 1) d += __shfl_xor_sync(0xFFFFFFFFu, d, o);
    if (lane == 0) out[warp] = d * invp[0] + mask[warp];
}

// ---------------- fused single-block topk, batched over t (blockIdx.x) ------
__global__ __launch_bounds__(1024) void topk_kernel(
    const float* __restrict__ scores_all, int k,
    int* __restrict__ idx_all, float* __restrict__ tv_all) {
    const float* scores = scores_all + (size_t)blockIdx.x * NN;
    int* idx_out = idx_all + blockIdx.x * k;
    float* tv_out = tv_all + blockIdx.x * k;
    __shared__ unsigned h1[1024];
    __shared__ unsigned csum[1024];
    __shared__ unsigned h2[64];
    __shared__ unsigned long long sk[4096];
    __shared__ int s_cb, s_kAbove, s_T16, s_cnt;
    int tid = threadIdx.x;
    h1[tid] = 0;
    if (tid < 64) h2[tid] = 0;
    if (tid == 0) s_cnt = 0;
    __syncthreads();

    const float4* s4 = reinterpret_cast<const float4*>(scores);
    for (int i = tid; i < NN / 4; i += 1024) {
        float4 v = s4[i];
        atomicAdd(&h1[sortable_u32(v.x) >> 22], 1u);
        atomicAdd(&h1[sortable_u32(v.y) >> 22], 1u);
        atomicAdd(&h1[sortable_u32(v.z) >> 22], 1u);
        atomicAdd(&h1[sortable_u32(v.w) >> 22], 1u);
    }
    __syncthreads();
    csum[tid] = h1[tid];
    __syncthreads();
    for (int off = 1; off < 1024; off <<= 1) {
        unsigned v = (tid + off < 1024) ? csum[tid + off] : 0u;
        __syncthreads();
        csum[tid] += v;
        __syncthreads();
    }
    unsigned above = (tid < 1023) ? csum[tid + 1] : 0u;
    if (csum[tid] >= (unsigned)k && above < (unsigned)k) { s_cb = tid; s_kAbove = (int)above; }
    __syncthreads();
    int cb = s_cb;
    unsigned kAbove = (unsigned)s_kAbove;

    for (int i = tid; i < NN / 4; i += 1024) {
        float4 v = s4[i];
        unsigned u;
        u = sortable_u32(v.x); if ((int)(u >> 22) == cb) atomicAdd(&h2[(u >> 16) & 63], 1u);
        u = sortable_u32(v.y); if ((int)(u >> 22) == cb) atomicAdd(&h2[(u >> 16) & 63], 1u);
        u = sortable_u32(v.z); if ((int)(u >> 22) == cb) atomicAdd(&h2[(u >> 16) & 63], 1u);
        u = sortable_u32(v.w); if ((int)(u >> 22) == cb) atomicAdd(&h2[(u >> 16) & 63], 1u);
    }
    __syncthreads();
    if (tid == 0) {
        unsigned run = kAbove;
        int f = 0;
        for (int b = 63; b >= 0; b--) {
            run += h2[b];
            if (run >= (unsigned)k) { f = b; break; }
        }
        s_T16 = (cb << 6) | f;
    }
    __syncthreads();
    int T16 = s_T16;

    for (int i = tid; i < NN / 4; i += 1024) {
        float4 v = s4[i];
        float vs[4] = {v.x, v.y, v.z, v.w};
#pragma unroll
        for (int c = 0; c < 4; c++) {
            unsigned u = sortable_u32(vs[c]);
            if ((int)(u >> 16) >= T16) {
                int p = atomicAdd(&s_cnt, 1);
                if (p < 4096) {
                    unsigned idx = (unsigned)(i * 4 + c);
                    sk[p] = ((unsigned long long)u << 32) |
                            (unsigned long long)(0xFFFFFFFFu - idx);
                }
            }
        }
    }
    __syncthreads();
    int cnt = s_cnt; if (cnt > 4096) cnt = 4096;
    int n = k; while (n < cnt) n <<= 1;
    for (int i = tid; i < n; i += 1024) if (i >= cnt) sk[i] = 0ULL;
    __syncthreads();
    for (int size = 2; size <= n; size <<= 1) {
        for (int stride = size >> 1; stride; stride >>= 1) {
            for (int i = tid; i < n; i += 1024) {
                int j = i ^ stride;
                if (j > i) {
                    bool asc = (i & size) != 0;
                    unsigned long long a = sk[i], b = sk[j];
                    if ((a > b) == asc) { sk[i] = b; sk[j] = a; }
                }
            }
            __syncthreads();
        }
    }
    if (tid < k) {
        unsigned long long key = sk[tid];
        int idx = (int)(0xFFFFFFFFu - (unsigned)(key & 0xFFFFFFFFu));
        if (idx < 0) idx = 0; if (idx >= NN) idx = NN - 1;   // safety
        idx_out[tid] = idx;
        tv_out[tid] = tanhf(scores[idx]);
    }
}

// ---------------- matrix GRU: one block per output column ----------------
template <int COLS>
__global__ __launch_bounds__(128) void gru_kernel(
    const float* __restrict__ X,
    const int* __restrict__ idx, const float* __restrict__ tv,
    const float* __restrict__ Wu, const float* __restrict__ Uu, const float* __restrict__ Bu,
    const float* __restrict__ Wr, const float* __restrict__ Ur, const float* __restrict__ Br,
    const float* __restrict__ Wh, const float* __restrict__ Uh, const float* __restrict__ Bh,
    const float* __restrict__ Qin, float* __restrict__ Qout) {
    __shared__ __align__(16) float zs[128];
    __shared__ __align__(16) float qs[128];
    __shared__ __align__(16) float rq[128];
    int c = blockIdx.x, r = threadIdx.x;
    zs[r] = X[(size_t)idx[c] * 128 + r] * tv[c];
    float q = Qin[r * COLS + c];
    qs[r] = q;
    __syncthreads();

    const float4* zr  = reinterpret_cast<const float4*>(zs);
    const float4* qr  = reinterpret_cast<const float4*>(qs);
    const float4* pwu = reinterpret_cast<const float4*>(Wu + r * 128);
    const float4* puu = reinterpret_cast<const float4*>(Uu + r * 128);
    const float4* pwr = reinterpret_cast<const float4*>(Wr + r * 128);
    const float4* pur = reinterpret_cast<const float4*>(Ur + r * 128);
    const float4* pwh = reinterpret_cast<const float4*>(Wh + r * 128);
    float au = 0.f, ar = 0.f, hw = 0.f;
#pragma unroll 8
    for (int i = 0; i < 32; i++) {
        float4 z4 = zr[i], q4 = qr[i];
        float4 a = pwu[i]; au += a.x * z4.x + a.y * z4.y + a.z * z4.z + a.w * z4.w;
        float4 b = puu[i]; au += b.x * q4.x + b.y * q4.y + b.z * q4.z + b.w * q4.w;
        float4 cc = pwr[i]; ar += cc.x * z4.x + cc.y * z4.y + cc.z * z4.z + cc.w * z4.w;
        float4 d = pur[i]; ar += d.x * q4.x + d.y * q4.y + d.z * q4.z + d.w * q4.w;
        float4 e = pwh[i]; hw += e.x * z4.x + e.y * z4.y + e.z * z4.z + e.w * z4.w;
    }
    float upd = 1.f / (1.f + expf(-(au + Bu[r * COLS + c])));
    float rst = 1.f / (1.f + expf(-(ar + Br[r * COLS + c])));
    rq[r] = rst * q;
    __syncthreads();
    const float4* puh = reinterpret_cast<const float4*>(Uh + r * 128);
    const float4* rq4 = reinterpret_cast<const float4*>(rq);
    float hu = 0.f;
#pragma unroll 8
    for (int i = 0; i < 32; i++) {
        float4 a = puh[i]; float4 v = rq4[i];
        hu += a.x * v.x + a.y * v.y + a.z * v.z + a.w * v.w;
    }
    float hcap = tanhf(hw + hu + Bh[r * COLS + c]);
    Qout[r * COLS + c] = (1.f - upd) * q + upd * hcap;
}

// ---- GEMM batched over t (blockIdx.y): OUT[t] = X[t] @ Q[t], K=128 (2x64 chunks)
// EPI: apply relu to output (h1) AND compute scores1 = relu_row @ scorer * inv + mask.
template <int BN, int TN, bool EPI>
__global__ __launch_bounds__(256) void gemm_kernel(
    const float* __restrict__ Xall, const float* __restrict__ Qall,
    float* __restrict__ OUTall,
    const float* __restrict__ scorer, const float* __restrict__ invp,
    const float* __restrict__ maskall, float* __restrict__ scall) {
    constexpr int PITCH = 132;
    extern __shared__ float smem[];
    float* Xs = smem;                     // [64][PITCH] transposed: Xs[k][m]
    float* Qs = smem + 64 * PITCH;        // [128][BN]
    const int tid = threadIdx.x;
    const int tx = tid & 15, ty = tid >> 4;
    const int m0 = blockIdx.x * 128;
    const int t  = blockIdx.y;
    const float* X   = Xall + (size_t)t * NN * 128;
    const float* Q   = Qall + (size_t)t * 128 * BN;
    float*       OUT = OUTall + (size_t)t * NN * BN;

    constexpr int QF4 = 128 * BN / 4;
    for (int f = tid; f < QF4; f += 256)
        reinterpret_cast<float4*>(Qs)[f] = reinterpret_cast<const float4*>(Q)[f];

    float acc[8][TN];
#pragma unroll
    for (int i = 0; i < 8; i++)
#pragma unroll
        for (int j = 0; j < TN; j++) acc[i][j] = 0.f;

    const int mb = ty * 8, nb = tx * TN;

#pragma unroll
    for (int kc = 0; kc < 2; kc++) {
        if (kc) __syncthreads();          // WAR: prev chunk's reads done
#pragma unroll
        for (int it = 0; it < 8; ++it) {
            int f = it * 256 + tid;
            int m = f >> 4, k4 = f & 15;
            float4 v = make_float4(0.f, 0.f, 0.f, 0.f);
            int gm = m0 + m;
            if (gm < NN) v = reinterpret_cast<const float4*>(X)[(size_t)gm * 32 + kc * 16 + k4];
            int k = k4 * 4;
            Xs[(k + 0) * PITCH + m] = v.x;
            Xs[(k + 1) * PITCH + m] = v.y;
            Xs[(k + 2) * PITCH + m] = v.z;
            Xs[(k + 3) * PITCH + m] = v.w;
        }
        __syncthreads();
#pragma unroll 4
        for (int k = 0; k < 64; k++) {
            float a[8], b[TN];
            float4 a0 = *reinterpret_cast<const float4*>(&Xs[k * PITCH + mb]);
            float4 a1 = *reinterpret_cast<const float4*>(&Xs[k * PITCH + mb + 4]);
            a[0] = a0.x; a[1] = a0.y; a[2] = a0.z; a[3] = a0.w;
            a[4] = a1.x; a[5] = a1.y; a[6] = a1.z; a[7] = a1.w;
#pragma unroll
            for (int j4 = 0; j4 < TN / 4; j4++) {
                float4 bq = *reinterpret_cast<const float4*>(&Qs[(kc * 64 + k) * BN + nb + j4 * 4]);
                b[j4 * 4 + 0] = bq.x; b[j4 * 4 + 1] = bq.y;
                b[j4 * 4 + 2] = bq.z; b[j4 * 4 + 3] = bq.w;
            }
#pragma unroll
            for (int i = 0; i < 8; i++)
#pragma unroll
                for (int j = 0; j < TN; j++)
                    acc[i][j] = fmaf(a[i], b[j], acc[i][j]);
        }
    }

    if (EPI) {
        // relu in-place
#pragma unroll
        for (int i = 0; i < 8; i++)
#pragma unroll
            for (int j = 0; j < TN; j++) acc[i][j] = fmaxf(acc[i][j], 0.f);
    }

#pragma unroll
    for (int i = 0; i < 8; i++) {
        int gm = m0 + mb + i;
        if (gm < NN) {
#pragma unroll
            for (int j4 = 0; j4 < TN / 4; j4++) {
                float4 o;
                o.x = acc[i][j4 * 4 + 0]; o.y = acc[i][j4 * 4 + 1];
                o.z = acc[i][j4 * 4 + 2]; o.w = acc[i][j4 * 4 + 3];
                reinterpret_cast<float4*>(OUT + (size_t)gm * BN + nb)[j4] = o;
            }
        }
    }

    if (EPI) {
        // scores1[row] = (relu_row @ scorer) * inv + mask[row]
        const float* mask = maskall + (size_t)t * NN;
        float*       sc   = scall + (size_t)t * NN;
        float scr[TN];
#pragma unroll
        for (int j = 0; j < TN; j++) scr[j] = scorer[nb + j];
        float iv = invp[0];
#pragma unroll
        for (int i = 0; i < 8; i++) {
            float p = 0.f;
#pragma unroll
            for (int j = 0; j < TN; j++) p = fmaf(acc[i][j], scr[j], p);
            // reduce across the 16 tx lanes (same ty = same 16-lane half-warp)
            p += __shfl_xor_sync(0xFFFFFFFFu, p, 8);
            p += __shfl_xor_sync(0xFFFFFFFFu, p, 4);
            p += __shfl_xor_sync(0xFFFFFFFFu, p, 2);
            p += __shfl_xor_sync(0xFFFFFFFFu, p, 1);
            int gm = m0 + mb + i;
            if (tx == 0 && gm < NN) sc[gm] = p * iv + mask[gm];
        }
    }
}

// ---------------- batched CSR build (all timesteps) ----------------
__global__ void deg_all_kernel(const int* __restrict__ dst, int* __restrict__ deg) {
    int i = blockIdx.x * blockDim.x + threadIdx.x;   // flat (t,e)
    if (i < TT * EE) {
        int t = i / EE;
        atomicAdd(&deg[t * NN + dst[i]], 1);
    }
}

__global__ __launch_bounds__(1024) void scan_all_kernel(int* __restrict__ deg_all,
                                                        int* __restrict__ rowptr_all) {
    __shared__ int sums[1024];
    int* deg = deg_all + blockIdx.x * NN;
    int* rowptr = rowptr_all + blockIdx.x * (NN + 1);
    int tid = threadIdx.x;
    const int CH = (NN + 1023) / 1024;   // 49
    int s0 = tid * CH;
    int s = 0;
    for (int j = 0; j < CH; j++) {
        int i = s0 + j;
        if (i < NN) s += deg[i];
    }
    sums[tid] = s;
    __syncthreads();
    for (int off = 1; off < 1024; off <<= 1) {
        int v = (tid >= off) ? sums[tid - off] : 0;
        __syncthreads();
        sums[tid] += v;
        __syncthreads();
    }
    int run = (tid == 0) ? 0 : sums[tid - 1];
    for (int j = 0; j < CH; j++) {
        int i = s0 + j;
        if (i < NN) {
            int d = deg[i];
            rowptr[i] = run;
            deg[i] = run;    // cursor
            run += d;
        }
    }
    if (tid == 1023) rowptr[NN] = sums[1023];
}

// fill CSR with src/w directly (drop eid indirection)
__global__ void fill_all_kernel(const int* __restrict__ dst, const int* __restrict__ src,
                                const float* __restrict__ ew,
                                int* __restrict__ cursor,
                                int* __restrict__ csrc, float* __restrict__ csrw) {
    int i = blockIdx.x * blockDim.x + threadIdx.x;   // flat (t,e)
    if (i < TT * EE) {
        int t = i / EE;
        int p = atomicAdd(&cursor[t * NN + dst[i]], 1);
        csrc[t * EE + p] = src[i];
        csrw[t * EE + p] = ew[i];
    }
}

// ---------------- gather AX[t][d] = sum_e w_e * X[t][src_e]  (128 cols, batched t)
__global__ __launch_bounds__(256) void gatherAX_kernel(
    const float* __restrict__ Xall, const int* __restrict__ rowptr,
    const int* __restrict__ csrc, const float* __restrict__ csrw,
    float* __restrict__ AXall) {
    int warp = (blockIdx.x * blockDim.x + threadIdx.x) >> 5;  // flat (t,node)
    int lane = threadIdx.x & 31;
    if (warp >= TT * NN) return;
    int t = warp / NN, node = warp - t * NN;
    const int* rp = rowptr + (size_t)t * (NN + 1) + node;
    const int* sp = csrc + (size_t)t * EE;
    const float* wp = csrw + (size_t)t * EE;
    const float4* X4 = reinterpret_cast<const float4*>(Xall + (size_t)t * NN * 128);
    int b = rp[0], e2 = rp[1];
    float4 acc = make_float4(0.f, 0.f, 0.f, 0.f);
    for (int j = b; j < e2; j++) {
        int s = sp[j];
        float w = wp[j];
        float4 v = X4[(size_t)s * 32 + lane];
        acc.x = fmaf(w, v.x, acc.x);
        acc.y = fmaf(w, v.y, acc.y);
        acc.z = fmaf(w, v.z, acc.z);
        acc.w = fmaf(w, v.w, acc.w);
    }
    reinterpret_cast<float4*>(AXall)[(size_t)warp * 32 + lane] = acc;
}

// ---------------- final gather: out[t][d] = relu(sum_e w_e XW1[t][src_e]) (64 cols)
__global__ __launch_bounds__(256) void gather64_kernel(
    const float* __restrict__ XWall, const int* __restrict__ rowptr,
    const int* __restrict__ csrc, const float* __restrict__ csrw,
    float* __restrict__ outall) {
    int warp = (blockIdx.x * blockDim.x + threadIdx.x) >> 5;
    int lane = threadIdx.x & 31;
    int f = warp * 2 + (lane >> 4);      // flat (t,node), 2 nodes/warp
    int cl = lane & 15;
    if (f >= TT * NN) return;
    int t = f / NN, node = f - t * NN;
    const int* rp = rowptr + (size_t)t * (NN + 1) + node;
    const int* sp = csrc + (size_t)t * EE;
    const float* wp = csrw + (size_t)t * EE;
    const float4* XW4 = reinterpret_cast<const float4*>(XWall + (size_t)t * NN * 64);
    int b = rp[0], e2 = rp[1];
    float4 acc = make_float4(0.f, 0.f, 0.f, 0.f);
    for (int j = b; j < e2; j++) {
        int s = sp[j];
        float w = wp[j];
        float4 v = XW4[(size_t)s * 16 + cl];
        acc.x = fmaf(w, v.x, acc.x);
        acc.y = fmaf(w, v.y, acc.y);
        acc.z = fmaf(w, v.z, acc.z);
        acc.w = fmaf(w, v.w, acc.w);
    }
    acc.x = fmaxf(acc.x, 0.f); acc.y = fmaxf(acc.y, 0.f);
    acc.z = fmaxf(acc.z, 0.f); acc.w = fmaxf(acc.w, 0.f);
    reinterpret_cast<float4*>(outall)[(size_t)f * 16 + cl] = acc;
}

// ---------------- host orchestration ----------------
extern "C" void kernel_launch(void* const* d_in, const int* in_sizes, int n_in,
                              void* d_out, int out_size) {
    const float* node_embs = (const float*)d_in[0];
    const float* mask      = (const float*)d_in[1];
    const int*   esrc      = (const int*)d_in[2];
    const int*   edst      = (const int*)d_in[3];
    const float* ew        = (const float*)d_in[4];
    const float* gcn_w0    = (const float*)d_in[5];
    const float* gcn_w1    = (const float*)d_in[6];
    const float* L0[10]; for (int i = 0; i < 10; i++) L0[i] = (const float*)d_in[7 + i];
    const float* L1[10]; for (int i = 0; i < 10; i++) L1[i] = (const float*)d_in[17 + i];
    float* out = (float*)d_out;

    float *scores0, *scores1, *tv0, *tv1, *inv, *q0s, *q1s, *ax, *h1, *xw1, *csrw;
    int *idx0, *idx1, *rowptr, *cursor, *csrc;
    cudaGetSymbolAddress((void**)&scores0, g_scores0);
    cudaGetSymbolAddress((void**)&scores1, g_scores1);
    cudaGetSymbolAddress((void**)&idx0,    g_idx0);
    cudaGetSymbolAddress((void**)&tv0,     g_tv0);
    cudaGetSymbolAddress((void**)&idx1,    g_idx1);
    cudaGetSymbolAddress((void**)&tv1,     g_tv1);
    cudaGetSymbolAddress((void**)&inv,     g_inv);
    cudaGetSymbolAddress((void**)&q0s,     g_Q0s);
    cudaGetSymbolAddress((void**)&q1s,     g_Q1s);
    cudaGetSymbolAddress((void**)&ax,      g_AX);
    cudaGetSymbolAddress((void**)&h1,      g_h1);
    cudaGetSymbolAddress((void**)&xw1,     g_XW1);
    cudaGetSymbolAddress((void**)&rowptr,  g_rowptr);
    cudaGetSymbolAddress((void**)&cursor,  g_cursor);
    cudaGetSymbolAddress((void**)&csrc,    g_csrc);
    cudaGetSymbolAddress((void**)&csrw,    g_csrw);

    // one-time host objects: 1 stream + 2 events (same passing footprint as R9/R12)
    static cudaStream_t sB = nullptr;
    static cudaEvent_t evStart, evCSR;
    if (!sB) {
        cudaStreamCreateWithFlags(&sB, cudaStreamNonBlocking);
        cudaEventCreateWithFlags(&evStart, cudaEventDisableTiming);
        cudaEventCreateWithFlags(&evCSR,   cudaEventDisableTiming);
    }

    size_t sm128 = (size_t)(64 * 132 + 128 * 128) * sizeof(float);  // 99328
    size_t sm64  = (size_t)(64 * 132 + 128 * 64)  * sizeof(float);  // 66560
    cudaFuncSetAttribute((const void*)gemm_kernel<128, 8, true>,
                         cudaFuncAttributeMaxDynamicSharedMemorySize, (int)sm128);
    cudaFuncSetAttribute((const void*)gemm_kernel<64, 4, false>,
                         cudaFuncAttributeMaxDynamicSharedMemorySize, (int)sm64);

    const int gblocks = (NN + 127) / 128;

    // ---- fork: sB builds CSR while origin does scores0/topk0/gru0 ----
    cudaEventRecord(evStart, 0);
    cudaStreamWaitEvent(sB, evStart, 0);

    cudaMemsetAsync(cursor, 0, (size_t)TT * NN * sizeof(int), sB);
    deg_all_kernel<<<(TT * EE + 255) / 256, 256, 0, sB>>>(edst, cursor);
    scan_all_kernel<<<TT, 1024, 0, sB>>>(cursor, rowptr);
    fill_all_kernel<<<(TT * EE + 255) / 256, 256, 0, sB>>>(edst, esrc, ew, cursor, csrc, csrw);
    cudaEventRecord(evCSR, sB);

    norm_kernel<<<2, 128>>>(L0[9], L1[9], inv);
    scores0_all_kernel<<<(TT * NN + 7) / 8, 256>>>(node_embs, L0[9], mask, inv, scores0);
    topk_kernel<<<TT, 1024>>>(scores0, 128, idx0, tv0);           // batched, 4 parallel blocks
    for (int t = 0; t < TT; t++) {
        const float* Xt   = node_embs + (size_t)t * NN * F0;
        const float* q0in = (t == 0) ? gcn_w0 : (q0s + (size_t)(t - 1) * 128 * 128);
        gru_kernel<128><<<128, 128>>>(Xt, idx0 + t * 128, tv0 + t * 128,
                                      L0[0], L0[1], L0[2], L0[3], L0[4],
                                      L0[5], L0[6], L0[7], L0[8],
                                      q0in, q0s + (size_t)t * 128 * 128);
    }

    // ---- join CSR, then the batched main chain on origin ----
    cudaStreamWaitEvent(0, evCSR, 0);

    // AX[t] = A(t) @ X(t)  — all timesteps, no other deps
    gatherAX_kernel<<<(TT * NN * 32 + 255) / 256, 256>>>(node_embs, rowptr, csrc, csrw, ax);

    // h1[t] = relu(AX[t] @ Q0[t]);  scores1[t] fused in epilogue
    gemm_kernel<128, 8, true><<<dim3(gblocks, TT), 256, sm128>>>(
        ax, q0s, h1, L1[9], inv + 1, mask, scores1);

    // layer-1 topk (batched) + serial gru chain
    topk_kernel<<<TT, 1024>>>(scores1, 64, idx1, tv1);
    for (int t = 0; t < TT; t++) {
        const float* q1in = (t == 0) ? gcn_w1 : (q1s + (size_t)(t - 1) * 128 * 64);
        gru_kernel<64><<<64, 128>>>(h1 + (size_t)t * NN * 128, idx1 + t * 64, tv1 + t * 64,
                                    L1[0], L1[1], L1[2], L1[3], L1[4],
                                    L1[5], L1[6], L1[7], L1[8],
                                    q1in, q1s + (size_t)t * 128 * 64);
    }

    // XW1[t] = h1[t] @ Q1[t]  (batched)
    gemm_kernel<64, 4, false><<<dim3(gblocks, TT), 256, sm64>>>(
        h1, q1s, xw1, nullptr, nullptr, nullptr, nullptr);

    // out[t] = relu(A(t) @ XW1[t])  (batched)
    gather64_kernel<<<(((TT * NN + 1) / 2) * 32 + 255) / 256, 256>>>(
        xw1, rowptr, csrc, csrw, out);
}